// round 1
// baseline (speedup 1.0000x reference)
#include <cuda_runtime.h>
#include <cstdint>

#define N_NODES 100000
#define N_EDGES 800000
#define F_IN    128
#define C_MID   256
#define H_DIM   128
#define O_DIM   6
#define NEG_SLOPE 0.2f

// total edges including self-loops
#define E_TOT (N_EDGES + N_NODES)

// ---------------- device scratch (no allocations allowed) ----------------
__device__ float g_xw[(size_t)N_NODES * C_MID];    // x @ W            102.4 MB
__device__ float g_gat[(size_t)N_NODES * C_MID];   // GAT accum / h2   102.4 MB
__device__ float g_h3[(size_t)N_NODES * H_DIM];    // fc2 output        51.2 MB
__device__ float g_s[N_NODES];
__device__ float g_d[N_NODES];
__device__ float g_denom[N_NODES];

// ---------------- zero accumulators ----------------
__global__ void zero_kernel() {
    const int stride = gridDim.x * blockDim.x;
    int idx = blockIdx.x * blockDim.x + threadIdx.x;
    const int total4 = N_NODES * C_MID / 4;
    float4 z = make_float4(0.f, 0.f, 0.f, 0.f);
    for (int i = idx; i < total4; i += stride)
        reinterpret_cast<float4*>(g_gat)[i] = z;
    for (int i = idx; i < N_NODES; i += stride)
        g_denom[i] = 0.f;
}

// ---------------- SGEMM 128x128 tile, BK=8, 256 threads, 8x8 per thread ----------------
// EPI: 0 = plain store, 1 = relu(acc + bias[col])
template <int EPI>
__global__ __launch_bounds__(256) void sgemm128(
    const float* __restrict__ A, const float* __restrict__ B,
    const float* __restrict__ bias, float* __restrict__ C,
    int M, int N, int K)
{
    constexpr int BM = 128, BN = 128, BK = 8;
    __shared__ float As[BK][BM];
    __shared__ float Bs[BK][BN];

    const int tid = threadIdx.x;
    const int tx = tid % 16;       // column group
    const int ty = tid / 16;       // row group
    const int row0 = blockIdx.y * BM;
    const int col0 = blockIdx.x * BN;

    // global load indexing
    const int a_row = tid >> 1;          // 0..127
    const int a_col = (tid & 1) * 4;     // 0 or 4
    const int b_row = tid >> 5;          // 0..7
    const int b_col = (tid & 31) * 4;    // 0..124

    float acc[8][8];
#pragma unroll
    for (int i = 0; i < 8; i++)
#pragma unroll
        for (int j = 0; j < 8; j++) acc[i][j] = 0.f;

    for (int k0 = 0; k0 < K; k0 += BK) {
        // load A tile (transposed into As[k][m])
        float4 av = make_float4(0.f, 0.f, 0.f, 0.f);
        const int gr = row0 + a_row;
        if (gr < M)
            av = *reinterpret_cast<const float4*>(A + (size_t)gr * K + k0 + a_col);
        As[a_col + 0][a_row] = av.x;
        As[a_col + 1][a_row] = av.y;
        As[a_col + 2][a_row] = av.z;
        As[a_col + 3][a_row] = av.w;
        // load B tile
        *reinterpret_cast<float4*>(&Bs[b_row][b_col]) =
            *reinterpret_cast<const float4*>(B + (size_t)(k0 + b_row) * N + col0 + b_col);
        __syncthreads();

#pragma unroll
        for (int k = 0; k < BK; k++) {
            float a_frag[8], b_frag[8];
#pragma unroll
            for (int i = 0; i < 8; i++) a_frag[i] = As[k][ty * 8 + i];
#pragma unroll
            for (int j = 0; j < 8; j++) b_frag[j] = Bs[k][tx * 8 + j];
#pragma unroll
            for (int i = 0; i < 8; i++)
#pragma unroll
                for (int j = 0; j < 8; j++)
                    acc[i][j] = fmaf(a_frag[i], b_frag[j], acc[i][j]);
        }
        __syncthreads();
    }

#pragma unroll
    for (int i = 0; i < 8; i++) {
        const int r = row0 + ty * 8 + i;
        if (r >= M) break;
#pragma unroll
        for (int j = 0; j < 8; j += 4) {
            const int c = col0 + tx * 8 + j;
            float4 v = make_float4(acc[i][j], acc[i][j + 1], acc[i][j + 2], acc[i][j + 3]);
            if (EPI == 1) {
                v.x = fmaxf(v.x + bias[c + 0], 0.f);
                v.y = fmaxf(v.y + bias[c + 1], 0.f);
                v.z = fmaxf(v.z + bias[c + 2], 0.f);
                v.w = fmaxf(v.w + bias[c + 3], 0.f);
            }
            *reinterpret_cast<float4*>(C + (size_t)r * N + c) = v;
        }
    }
}

// ---------------- per-node attention halves: s[i]=xw[i].a_src, d[i]=xw[i].a_dst ----------------
__global__ void alpha_kernel(const float* __restrict__ a_src,
                             const float* __restrict__ a_dst)
{
    const int warp = (blockIdx.x * blockDim.x + threadIdx.x) >> 5;
    const int lane = threadIdx.x & 31;
    if (warp >= N_NODES) return;
    const float* row = g_xw + (size_t)warp * C_MID;
    float s = 0.f, d = 0.f;
#pragma unroll
    for (int c = lane; c < C_MID; c += 32) {
        const float v = row[c];
        s = fmaf(v, a_src[c], s);
        d = fmaf(v, a_dst[c], d);
    }
#pragma unroll
    for (int o = 16; o > 0; o >>= 1) {
        s += __shfl_down_sync(0xffffffffu, s, o);
        d += __shfl_down_sync(0xffffffffu, d, o);
    }
    if (lane == 0) { g_s[warp] = s; g_d[warp] = d; }
}

// ---------------- edge scatter: gat[dst] += exp(lrelu(s[src]+d[dst])) * xw[src] ----------------
// 64 threads per edge, each handles 4 floats (float4 gather + vector RED).
__global__ void edge_kernel(const int* __restrict__ edge_index)
{
    const int gid = blockIdx.x * blockDim.x + threadIdx.x;
    const int eid = gid >> 6;       // 64 threads / edge
    const int t   = gid & 63;
    if (eid >= E_TOT) return;

    int src, dst;
    if (eid < N_EDGES) {
        src = edge_index[eid];
        dst = edge_index[N_EDGES + eid];
    } else {
        src = dst = eid - N_EDGES;
    }

    float e = g_s[src] + g_d[dst];
    e = (e > 0.f) ? e : NEG_SLOPE * e;
    const float w = expf(e);   // softmax max-shift cancels exactly; e is O(1), safe

    if (t == 0) atomicAdd(&g_denom[dst], w);

    const float4 v = *reinterpret_cast<const float4*>(g_xw + (size_t)src * C_MID + t * 4);
    float* p = g_gat + (size_t)dst * C_MID + t * 4;
    asm volatile("red.global.add.v4.f32 [%0], {%1, %2, %3, %4};"
                 :: "l"(p), "f"(v.x * w), "f"(v.y * w), "f"(v.z * w), "f"(v.w * w)
                 : "memory");
}

// ---------------- normalize + bias + relu (in place: gat -> h2) ----------------
__global__ void norm_kernel(const float* __restrict__ bias)
{
    const int i = blockIdx.x * blockDim.x + threadIdx.x;  // over N_NODES * 64 float4s
    if (i >= N_NODES * (C_MID / 4)) return;
    const int node = i >> 6;          // / 64
    const int c4 = i & 63;
    const float inv = 1.f / g_denom[node];
    float4 v = reinterpret_cast<float4*>(g_gat)[i];
    const float4 bb = reinterpret_cast<const float4*>(bias)[c4];
    v.x = fmaxf(fmaf(v.x, inv, bb.x), 0.f);
    v.y = fmaxf(fmaf(v.y, inv, bb.y), 0.f);
    v.z = fmaxf(fmaf(v.z, inv, bb.z), 0.f);
    v.w = fmaxf(fmaf(v.w, inv, bb.w), 0.f);
    reinterpret_cast<float4*>(g_gat)[i] = v;
}

// ---------------- final tiny GEMM: out = h3 @ W_out + b_out, one warp per row ----------------
__global__ void out_kernel(const float* __restrict__ W_out,
                           const float* __restrict__ b_out,
                           float* __restrict__ out)
{
    const int warp = (blockIdx.x * blockDim.x + threadIdx.x) >> 5;
    const int lane = threadIdx.x & 31;
    if (warp >= N_NODES) return;
    const float* row = g_h3 + (size_t)warp * H_DIM;
    float acc[O_DIM];
#pragma unroll
    for (int j = 0; j < O_DIM; j++) acc[j] = 0.f;
#pragma unroll
    for (int kk = 0; kk < H_DIM; kk += 32) {
        const float v = row[kk + lane];
        const float* wrow = W_out + (size_t)(kk + lane) * O_DIM;
#pragma unroll
        for (int j = 0; j < O_DIM; j++) acc[j] = fmaf(v, wrow[j], acc[j]);
    }
#pragma unroll
    for (int j = 0; j < O_DIM; j++)
#pragma unroll
        for (int o = 16; o > 0; o >>= 1)
            acc[j] += __shfl_down_sync(0xffffffffu, acc[j], o);
    if (lane == 0) {
#pragma unroll
        for (int j = 0; j < O_DIM; j++)
            out[(size_t)warp * O_DIM + j] = acc[j] + b_out[j];
    }
}

// ---------------- launch ----------------
extern "C" void kernel_launch(void* const* d_in, const int* in_sizes, int n_in,
                              void* d_out, int out_size)
{
    const float* x      = (const float*)d_in[0];
    const int*   ei     = (const int*)  d_in[1];
    const float* W      = (const float*)d_in[2];
    const float* a_src  = (const float*)d_in[3];
    const float* a_dst  = (const float*)d_in[4];
    const float* b      = (const float*)d_in[5];
    const float* W_fc2  = (const float*)d_in[6];
    const float* b_fc2  = (const float*)d_in[7];
    const float* W_out  = (const float*)d_in[8];
    const float* b_out  = (const float*)d_in[9];
    float* out = (float*)d_out;

    float *xw, *gat, *h3;
    cudaGetSymbolAddress((void**)&xw,  g_xw);
    cudaGetSymbolAddress((void**)&gat, g_gat);
    cudaGetSymbolAddress((void**)&h3,  g_h3);

    // 1) zero accumulators
    zero_kernel<<<2048, 256>>>();

    // 2) xw = x @ W   (100000 x 256, K=128)
    {
        dim3 grid(C_MID / 128, (N_NODES + 127) / 128);
        sgemm128<0><<<grid, 256>>>(x, W, nullptr, xw, N_NODES, C_MID, F_IN);
    }

    // 3) per-node attention scalars
    alpha_kernel<<<(N_NODES * 32 + 255) / 256, 256>>>(a_src, a_dst);

    // 4) edge scatter (fused softmax numerator + denominator)
    {
        const long long threads = (long long)E_TOT * 64;
        edge_kernel<<<(unsigned)((threads + 255) / 256), 256>>>(ei);
    }

    // 5) normalize + bias + relu  (gat -> h2, in place)
    norm_kernel<<<(N_NODES * (C_MID / 4) + 255) / 256, 256>>>(b);

    // 6) h3 = relu(h2 @ W_fc2 + b_fc2)   (100000 x 128, K=256)
    {
        dim3 grid(H_DIM / 128, (N_NODES + 127) / 128);
        sgemm128<1><<<grid, 256>>>(gat, W_fc2, b_fc2, h3, N_NODES, H_DIM, C_MID);
    }

    // 7) out = h3 @ W_out + b_out
    out_kernel<<<(N_NODES * 32 + 255) / 256, 256>>>(W_out, b_out, out);
}

// round 2
// speedup vs baseline: 1.3374x; 1.3374x over previous
#include <cuda_runtime.h>
#include <cstdint>

#define N_NODES 100000
#define N_EDGES 800000
#define F_IN    128
#define C_MID   256
#define H_DIM   128
#define O_DIM   6
#define NEG_SLOPE 0.2f

#define E_TOT (N_EDGES + N_NODES)
#define SCAN_BLK 1024
#define N_SCAN_BLKS ((N_NODES + SCAN_BLK - 1) / SCAN_BLK)   // 98

// ---------------- device scratch ----------------
__device__ float g_xw[(size_t)N_NODES * C_MID];    // x @ W            102.4 MB
__device__ float g_gat[(size_t)N_NODES * C_MID];   // h2 (post relu)   102.4 MB
__device__ float g_h3[(size_t)N_NODES * H_DIM];    // fc2 output        51.2 MB
__device__ float g_s[N_NODES];
__device__ float g_d[N_NODES];
__device__ int   g_count[N_NODES];
__device__ int   g_rowptr[N_NODES];
__device__ int   g_fill[N_NODES];
__device__ int   g_partial[N_SCAN_BLKS];
__device__ int   g_ecol[E_TOT];                    // src per CSR slot   3.6 MB

// ---------------- init small arrays ----------------
__global__ void init_kernel() {
    const int i = blockIdx.x * blockDim.x + threadIdx.x;
    if (i < N_NODES) {
        g_count[i] = 0;
        g_fill[i]  = 0;
        g_s[i] = 0.f;
        g_d[i] = 0.f;
    }
}

// ---------------- CSR build ----------------
__global__ void hist_kernel(const int* __restrict__ ei) {
    const int e = blockIdx.x * blockDim.x + threadIdx.x;
    if (e >= E_TOT) return;
    const int dst = (e < N_EDGES) ? ei[N_EDGES + e] : (e - N_EDGES);
    atomicAdd(&g_count[dst], 1);
}

__global__ void scan1_kernel() {
    __shared__ int sh[SCAN_BLK];
    const int i = blockIdx.x * SCAN_BLK + threadIdx.x;
    const int v = (i < N_NODES) ? g_count[i] : 0;
    sh[threadIdx.x] = v;
    __syncthreads();
    for (int off = 1; off < SCAN_BLK; off <<= 1) {
        const int t = (threadIdx.x >= off) ? sh[threadIdx.x - off] : 0;
        __syncthreads();
        sh[threadIdx.x] += t;
        __syncthreads();
    }
    if (i < N_NODES) g_rowptr[i] = sh[threadIdx.x] - v;   // exclusive
    if (threadIdx.x == SCAN_BLK - 1) g_partial[blockIdx.x] = sh[SCAN_BLK - 1];
}

__global__ void scan2_kernel() {
    if (threadIdx.x == 0 && blockIdx.x == 0) {
        int acc = 0;
        for (int b = 0; b < N_SCAN_BLKS; b++) {
            const int t = g_partial[b];
            g_partial[b] = acc;
            acc += t;
        }
    }
}

__global__ void scan3_kernel() {
    const int i = blockIdx.x * blockDim.x + threadIdx.x;
    if (i < N_NODES) g_rowptr[i] += g_partial[i >> 10];
}

__global__ void scatter_kernel(const int* __restrict__ ei) {
    const int e = blockIdx.x * blockDim.x + threadIdx.x;
    if (e >= E_TOT) return;
    int src, dst;
    if (e < N_EDGES) { src = ei[e]; dst = ei[N_EDGES + e]; }
    else             { src = dst = e - N_EDGES; }
    const int pos = g_rowptr[dst] + atomicAdd(&g_fill[dst], 1);
    g_ecol[pos] = src;
}

// ---------------- SGEMM 128x128 tile, BK=8, 256 threads, 8x8 per thread ----------------
// EPI: 0 = plain store, 1 = relu(acc + bias[col]),
//      2 = plain store + fused per-row dot with a_src/a_dst (atomicAdd into g_s/g_d)
template <int EPI>
__global__ __launch_bounds__(256) void sgemm128(
    const float* __restrict__ A, const float* __restrict__ B,
    const float* __restrict__ bias, float* __restrict__ C,
    const float* __restrict__ a_src, const float* __restrict__ a_dst,
    int M, int N, int K)
{
    constexpr int BM = 128, BN = 128, BK = 8;
    __shared__ float sh[2048];                 // reused: As|Bs, then reductions
    float (*As)[BM] = reinterpret_cast<float(*)[BM]>(sh);
    float (*Bs)[BN] = reinterpret_cast<float(*)[BN]>(sh + BK * BM);

    const int tid = threadIdx.x;
    const int tx = tid % 16;
    const int ty = tid / 16;
    const int row0 = blockIdx.y * BM;
    const int col0 = blockIdx.x * BN;

    const int a_row = tid >> 1;
    const int a_col = (tid & 1) * 4;
    const int b_row = tid >> 5;
    const int b_col = (tid & 31) * 4;

    float acc[8][8];
#pragma unroll
    for (int i = 0; i < 8; i++)
#pragma unroll
        for (int j = 0; j < 8; j++) acc[i][j] = 0.f;

    for (int k0 = 0; k0 < K; k0 += BK) {
        float4 av = make_float4(0.f, 0.f, 0.f, 0.f);
        const int gr = row0 + a_row;
        if (gr < M)
            av = *reinterpret_cast<const float4*>(A + (size_t)gr * K + k0 + a_col);
        As[a_col + 0][a_row] = av.x;
        As[a_col + 1][a_row] = av.y;
        As[a_col + 2][a_row] = av.z;
        As[a_col + 3][a_row] = av.w;
        *reinterpret_cast<float4*>(&Bs[b_row][b_col]) =
            *reinterpret_cast<const float4*>(B + (size_t)(k0 + b_row) * N + col0 + b_col);
        __syncthreads();

#pragma unroll
        for (int k = 0; k < BK; k++) {
            float a_frag[8], b_frag[8];
#pragma unroll
            for (int i = 0; i < 8; i++) a_frag[i] = As[k][ty * 8 + i];
#pragma unroll
            for (int j = 0; j < 8; j++) b_frag[j] = Bs[k][tx * 8 + j];
#pragma unroll
            for (int i = 0; i < 8; i++)
#pragma unroll
                for (int j = 0; j < 8; j++)
                    acc[i][j] = fmaf(a_frag[i], b_frag[j], acc[i][j]);
        }
        __syncthreads();
    }

    // store C
#pragma unroll
    for (int i = 0; i < 8; i++) {
        const int r = row0 + ty * 8 + i;
        if (r >= M) break;
#pragma unroll
        for (int j = 0; j < 8; j += 4) {
            const int c = col0 + tx * 8 + j;
            float4 v = make_float4(acc[i][j], acc[i][j + 1], acc[i][j + 2], acc[i][j + 3]);
            if (EPI == 1) {
                v.x = fmaxf(v.x + bias[c + 0], 0.f);
                v.y = fmaxf(v.y + bias[c + 1], 0.f);
                v.z = fmaxf(v.z + bias[c + 2], 0.f);
                v.w = fmaxf(v.w + bias[c + 3], 0.f);
            }
            *reinterpret_cast<float4*>(C + (size_t)r * N + c) = v;
        }
    }

    if (EPI == 2) {
        // fused attention halves: s[r] += sum_c acc[r][c]*a_src[c]; likewise d.
        float av[8], dv[8];
#pragma unroll
        for (int j = 0; j < 8; j++) {
            av[j] = a_src[col0 + tx * 8 + j];
            dv[j] = a_dst[col0 + tx * 8 + j];
        }
        __syncthreads();   // done with As/Bs
        // pass 1: s
#pragma unroll
        for (int i = 0; i < 8; i++) {
            float ps = 0.f;
#pragma unroll
            for (int j = 0; j < 8; j++) ps = fmaf(acc[i][j], av[j], ps);
            sh[(ty * 8 + i) * 16 + tx] = ps;
        }
        __syncthreads();
        if (tid < 128) {
            float s = 0.f;
#pragma unroll
            for (int t = 0; t < 16; t++) s += sh[tid * 16 + t];
            if (row0 + tid < M) atomicAdd(&g_s[row0 + tid], s);
        }
        __syncthreads();
        // pass 2: d
#pragma unroll
        for (int i = 0; i < 8; i++) {
            float pd = 0.f;
#pragma unroll
            for (int j = 0; j < 8; j++) pd = fmaf(acc[i][j], dv[j], pd);
            sh[(ty * 8 + i) * 16 + tx] = pd;
        }
        __syncthreads();
        if (tid < 128) {
            float d = 0.f;
#pragma unroll
            for (int t = 0; t < 16; t++) d += sh[tid * 16 + t];
            if (row0 + tid < M) atomicAdd(&g_d[row0 + tid], d);
        }
    }
}

// ---------------- CSR aggregate: per-node softmax-weighted sum + bias + relu ----------------
// 64 threads per node (2 warps), 4 nodes per 256-thread block.
__global__ __launch_bounds__(256) void aggregate_kernel(const float* __restrict__ bias)
{
    const int node = blockIdx.x * 4 + (threadIdx.x >> 6);
    const int t    = threadIdx.x & 63;
    if (node >= N_NODES) return;

    const int beg = g_rowptr[node];
    const int cnt = g_count[node];
    const float dterm = g_d[node];

    float4 acc = make_float4(0.f, 0.f, 0.f, 0.f);
    float wsum = 0.f;

    for (int k = 0; k < cnt; k++) {
        const int src = g_ecol[beg + k];                  // broadcast within warp
        float e = g_s[src] + dterm;                       // broadcast load
        e = (e > 0.f) ? e : NEG_SLOPE * e;
        const float w = __expf(e);                        // max-shift cancels exactly
        wsum += w;
        const float4 v = *reinterpret_cast<const float4*>(
            g_xw + (size_t)src * C_MID + t * 4);
        acc.x = fmaf(w, v.x, acc.x);
        acc.y = fmaf(w, v.y, acc.y);
        acc.z = fmaf(w, v.z, acc.z);
        acc.w = fmaf(w, v.w, acc.w);
    }

    const float inv = 1.f / wsum;                         // cnt >= 1 (self-loop)
    const float4 bb = reinterpret_cast<const float4*>(bias)[t];
    float4 o;
    o.x = fmaxf(fmaf(acc.x, inv, bb.x), 0.f);
    o.y = fmaxf(fmaf(acc.y, inv, bb.y), 0.f);
    o.z = fmaxf(fmaf(acc.z, inv, bb.z), 0.f);
    o.w = fmaxf(fmaf(acc.w, inv, bb.w), 0.f);
    *reinterpret_cast<float4*>(g_gat + (size_t)node * C_MID + t * 4) = o;
}

// ---------------- final tiny GEMM: out = h3 @ W_out + b_out ----------------
__global__ void out_kernel(const float* __restrict__ W_out,
                           const float* __restrict__ b_out,
                           float* __restrict__ out)
{
    const int warp = (blockIdx.x * blockDim.x + threadIdx.x) >> 5;
    const int lane = threadIdx.x & 31;
    if (warp >= N_NODES) return;
    const float* row = g_h3 + (size_t)warp * H_DIM;
    float acc[O_DIM];
#pragma unroll
    for (int j = 0; j < O_DIM; j++) acc[j] = 0.f;
#pragma unroll
    for (int kk = 0; kk < H_DIM; kk += 32) {
        const float v = row[kk + lane];
        const float* wrow = W_out + (size_t)(kk + lane) * O_DIM;
#pragma unroll
        for (int j = 0; j < O_DIM; j++) acc[j] = fmaf(v, wrow[j], acc[j]);
    }
#pragma unroll
    for (int j = 0; j < O_DIM; j++)
#pragma unroll
        for (int o = 16; o > 0; o >>= 1)
            acc[j] += __shfl_down_sync(0xffffffffu, acc[j], o);
    if (lane == 0) {
#pragma unroll
        for (int j = 0; j < O_DIM; j++)
            out[(size_t)warp * O_DIM + j] = acc[j] + b_out[j];
    }
}

// ---------------- launch ----------------
extern "C" void kernel_launch(void* const* d_in, const int* in_sizes, int n_in,
                              void* d_out, int out_size)
{
    const float* x      = (const float*)d_in[0];
    const int*   ei     = (const int*)  d_in[1];
    const float* W      = (const float*)d_in[2];
    const float* a_src  = (const float*)d_in[3];
    const float* a_dst  = (const float*)d_in[4];
    const float* b      = (const float*)d_in[5];
    const float* W_fc2  = (const float*)d_in[6];
    const float* b_fc2  = (const float*)d_in[7];
    const float* W_out  = (const float*)d_in[8];
    const float* b_out  = (const float*)d_in[9];
    float* out = (float*)d_out;

    float *xw, *gat, *h3;
    cudaGetSymbolAddress((void**)&xw,  g_xw);
    cudaGetSymbolAddress((void**)&gat, g_gat);
    cudaGetSymbolAddress((void**)&h3,  g_h3);

    // 1) init small arrays (counts, fill, s, d)
    init_kernel<<<(N_NODES + 255) / 256, 256>>>();

    // 2) CSR build (independent of GEMM1)
    hist_kernel<<<(E_TOT + 255) / 256, 256>>>(ei);
    scan1_kernel<<<N_SCAN_BLKS, SCAN_BLK>>>();
    scan2_kernel<<<1, 32>>>();
    scan3_kernel<<<(N_NODES + 255) / 256, 256>>>();
    scatter_kernel<<<(E_TOT + 255) / 256, 256>>>(ei);

    // 3) xw = x @ W with fused s/d attention dots
    {
        dim3 grid(C_MID / 128, (N_NODES + 127) / 128);
        sgemm128<2><<<grid, 256>>>(x, W, nullptr, xw, a_src, a_dst,
                                   N_NODES, C_MID, F_IN);
    }

    // 4) CSR aggregate with fused softmax + bias + relu
    aggregate_kernel<<<(N_NODES + 3) / 4, 256>>>(b);

    // 5) h3 = relu(h2 @ W_fc2 + b_fc2)
    {
        dim3 grid(H_DIM / 128, (N_NODES + 127) / 128);
        sgemm128<1><<<grid, 256>>>(gat, W_fc2, b_fc2, h3, nullptr, nullptr,
                                   N_NODES, H_DIM, C_MID);
    }

    // 6) out = h3 @ W_out + b_out
    out_kernel<<<(N_NODES * 32 + 255) / 256, 256>>>(W_out, b_out, out);
}

// round 3
// speedup vs baseline: 1.3971x; 1.0446x over previous
#include <cuda_runtime.h>
#include <cstdint>

#define N_NODES 100000
#define N_EDGES 800000
#define F_IN    128
#define C_MID   256
#define H_DIM   128
#define O_DIM   6
#define NEG_SLOPE 0.2f

#define E_TOT (N_EDGES + N_NODES)
#define SCAN_BLK 1024
#define N_SCAN_BLKS ((N_NODES + SCAN_BLK - 1) / SCAN_BLK)   // 98

// ---------------- device scratch ----------------
__device__ float g_xw[(size_t)N_NODES * C_MID];    // x @ W            102.4 MB
__device__ float g_gat[(size_t)N_NODES * C_MID];   // h2 (post relu)   102.4 MB
__device__ float g_s[N_NODES];
__device__ float g_d[N_NODES];
__device__ int   g_count[N_NODES];
__device__ int   g_rowptr[N_NODES];
__device__ int   g_fill[N_NODES];
__device__ int   g_partial[N_SCAN_BLKS];
__device__ int   g_ecol[E_TOT];                    // src per CSR slot   3.6 MB

// ---------------- init small arrays ----------------
__global__ void init_kernel() {
    const int i = blockIdx.x * blockDim.x + threadIdx.x;
    if (i < N_NODES) {
        g_count[i] = 0;
        g_fill[i]  = 0;
        g_s[i] = 0.f;
        g_d[i] = 0.f;
    }
}

// ---------------- CSR build ----------------
__global__ void hist_kernel(const int* __restrict__ ei) {
    const int e = blockIdx.x * blockDim.x + threadIdx.x;
    if (e >= E_TOT) return;
    const int dst = (e < N_EDGES) ? ei[N_EDGES + e] : (e - N_EDGES);
    atomicAdd(&g_count[dst], 1);
}

__global__ void scan1_kernel() {
    __shared__ int sh[SCAN_BLK];
    const int i = blockIdx.x * SCAN_BLK + threadIdx.x;
    const int v = (i < N_NODES) ? g_count[i] : 0;
    sh[threadIdx.x] = v;
    __syncthreads();
    for (int off = 1; off < SCAN_BLK; off <<= 1) {
        const int t = (threadIdx.x >= off) ? sh[threadIdx.x - off] : 0;
        __syncthreads();
        sh[threadIdx.x] += t;
        __syncthreads();
    }
    if (i < N_NODES) g_rowptr[i] = sh[threadIdx.x] - v;   // exclusive within block
    if (threadIdx.x == SCAN_BLK - 1) g_partial[blockIdx.x] = sh[SCAN_BLK - 1];
}

__global__ void scan2_kernel() {
    __shared__ int sh[128];
    const int t = threadIdx.x;
    const int v = (t < N_SCAN_BLKS) ? g_partial[t] : 0;
    sh[t] = v;
    __syncthreads();
    for (int off = 1; off < 128; off <<= 1) {
        const int u = (t >= off) ? sh[t - off] : 0;
        __syncthreads();
        sh[t] += u;
        __syncthreads();
    }
    if (t < N_SCAN_BLKS) g_partial[t] = sh[t] - v;        // exclusive of block sums
}

__global__ void scan3_kernel() {
    const int i = blockIdx.x * blockDim.x + threadIdx.x;
    if (i < N_NODES) g_rowptr[i] += g_partial[i >> 10];
}

__global__ void scatter_kernel(const int* __restrict__ ei) {
    const int e = blockIdx.x * blockDim.x + threadIdx.x;
    if (e >= E_TOT) return;
    int src, dst;
    if (e < N_EDGES) { src = ei[e]; dst = ei[N_EDGES + e]; }
    else             { src = dst = e - N_EDGES; }
    const int pos = g_rowptr[dst] + atomicAdd(&g_fill[dst], 1);
    g_ecol[pos] = src;
}

// ---------------- double-buffered SGEMM 128x128, BK=8, 256 threads, 8x8/thread ----
// EPI 0: GEMM1 — store C=xw, plus fused per-row dots with a_src/a_dst -> g_s/g_d
// EPI 1: GEMM2 — relu(acc + bias) then fused 128->6 GEMM with W_out -> out (no C store)
template <int EPI>
__global__ __launch_bounds__(256) void sgemm_db(
    const float* __restrict__ A, const float* __restrict__ B,
    const float* __restrict__ bias, float* __restrict__ C,
    const float* __restrict__ v1,   // EPI0: a_src   EPI1: W_out
    const float* __restrict__ v2,   // EPI0: a_dst   EPI1: b_out
    float* __restrict__ outp,       // EPI1: final output
    int M, int N, int K)
{
    constexpr int BM = 128, BN = 128, BK = 8;
    __shared__ float As[2][BK][BM];
    __shared__ float Bs[2][BK][BN];
    __shared__ float red[2][BM][17];     // epilogue reductions

    const int tid = threadIdx.x;
    const int tx = tid % 16;
    const int ty = tid / 16;
    const int row0 = blockIdx.y * BM;
    const int col0 = blockIdx.x * BN;

    const int a_row = tid >> 1;          // 0..127
    const int a_col = (tid & 1) * 4;     // 0 or 4
    const int b_row = tid >> 5;          // 0..7
    const int b_col = (tid & 31) * 4;    // 0..124

    const int gr = row0 + a_row;
    const float* Aptr = A + (size_t)gr * K + a_col;
    const float* Bptr = B + (size_t)b_row * N + col0 + b_col;

    float acc[8][8];
#pragma unroll
    for (int i = 0; i < 8; i++)
#pragma unroll
        for (int j = 0; j < 8; j++) acc[i][j] = 0.f;

    // prologue: stage tile 0
    float4 a_st = make_float4(0.f, 0.f, 0.f, 0.f);
    if (gr < M) a_st = *reinterpret_cast<const float4*>(Aptr);
    float4 b_st = *reinterpret_cast<const float4*>(Bptr);
    As[0][a_col + 0][a_row] = a_st.x;
    As[0][a_col + 1][a_row] = a_st.y;
    As[0][a_col + 2][a_row] = a_st.z;
    As[0][a_col + 3][a_row] = a_st.w;
    *reinterpret_cast<float4*>(&Bs[0][b_row][b_col]) = b_st;
    __syncthreads();

    const int ntiles = K / BK;
    for (int t = 0; t < ntiles; t++) {
        const int cur = t & 1;
        const int nxt = cur ^ 1;
        // stage next tile (LDG overlaps compute)
        if (t + 1 < ntiles) {
            const int k0 = (t + 1) * BK;
            a_st = make_float4(0.f, 0.f, 0.f, 0.f);
            if (gr < M) a_st = *reinterpret_cast<const float4*>(Aptr + k0);
            b_st = *reinterpret_cast<const float4*>(Bptr + (size_t)k0 * N);
        }
#pragma unroll
        for (int k = 0; k < BK; k++) {
            float a_frag[8], b_frag[8];
#pragma unroll
            for (int i = 0; i < 8; i++) a_frag[i] = As[cur][k][ty * 8 + i];
#pragma unroll
            for (int j = 0; j < 8; j++) b_frag[j] = Bs[cur][k][tx * 8 + j];
#pragma unroll
            for (int i = 0; i < 8; i++)
#pragma unroll
                for (int j = 0; j < 8; j++)
                    acc[i][j] = fmaf(a_frag[i], b_frag[j], acc[i][j]);
        }
        if (t + 1 < ntiles) {
            As[nxt][a_col + 0][a_row] = a_st.x;
            As[nxt][a_col + 1][a_row] = a_st.y;
            As[nxt][a_col + 2][a_row] = a_st.z;
            As[nxt][a_col + 3][a_row] = a_st.w;
            *reinterpret_cast<float4*>(&Bs[nxt][b_row][b_col]) = b_st;
        }
        __syncthreads();
    }

    if (EPI == 0) {
        // store C
#pragma unroll
        for (int i = 0; i < 8; i++) {
            const int r = row0 + ty * 8 + i;
            if (r >= M) break;
#pragma unroll
            for (int j = 0; j < 8; j += 4) {
                const int c = col0 + tx * 8 + j;
                float4 v = make_float4(acc[i][j], acc[i][j + 1],
                                       acc[i][j + 2], acc[i][j + 3]);
                *reinterpret_cast<float4*>(C + (size_t)r * N + c) = v;
            }
        }
        // fused attention halves
        float av[8], dv[8];
#pragma unroll
        for (int j = 0; j < 8; j++) {
            av[j] = v1[col0 + tx * 8 + j];
            dv[j] = v2[col0 + tx * 8 + j];
        }
#pragma unroll
        for (int i = 0; i < 8; i++) {
            float ps = 0.f, pd = 0.f;
#pragma unroll
            for (int j = 0; j < 8; j++) {
                ps = fmaf(acc[i][j], av[j], ps);
                pd = fmaf(acc[i][j], dv[j], pd);
            }
            red[0][ty * 8 + i][tx] = ps;
            red[1][ty * 8 + i][tx] = pd;
        }
        __syncthreads();
        if (tid < 128) {
            float s = 0.f, d = 0.f;
#pragma unroll
            for (int t = 0; t < 16; t++) {
                s += red[0][tid][t];
                d += red[1][tid][t];
            }
            if (row0 + tid < M) {
                atomicAdd(&g_s[row0 + tid], s);
                atomicAdd(&g_d[row0 + tid], d);
            }
        }
    } else {
        // EPI 1: relu(acc + bias) then out = h3 @ W_out + b_out, no C store
#pragma unroll
        for (int j = 0; j < 8; j++) {
            const float bb = bias[col0 + tx * 8 + j];
#pragma unroll
            for (int i = 0; i < 8; i++)
                acc[i][j] = fmaxf(acc[i][j] + bb, 0.f);
        }
        // outputs two at a time
        for (int o = 0; o < O_DIM; o += 2) {
            float w0[8], w1[8];
#pragma unroll
            for (int j = 0; j < 8; j++) {
                const int c = col0 + tx * 8 + j;
                w0[j] = v1[(size_t)c * O_DIM + o];
                w1[j] = v1[(size_t)c * O_DIM + o + 1];
            }
#pragma unroll
            for (int i = 0; i < 8; i++) {
                float p0 = 0.f, p1 = 0.f;
#pragma unroll
                for (int j = 0; j < 8; j++) {
                    p0 = fmaf(acc[i][j], w0[j], p0);
                    p1 = fmaf(acc[i][j], w1[j], p1);
                }
                red[0][ty * 8 + i][tx] = p0;
                red[1][ty * 8 + i][tx] = p1;
            }
            __syncthreads();
            if (tid < 128 && row0 + tid < M) {
                float s0 = 0.f, s1 = 0.f;
#pragma unroll
                for (int t = 0; t < 16; t++) {
                    s0 += red[0][tid][t];
                    s1 += red[1][tid][t];
                }
                outp[(size_t)(row0 + tid) * O_DIM + o]     = s0 + v2[o];
                outp[(size_t)(row0 + tid) * O_DIM + o + 1] = s1 + v2[o + 1];
            }
            __syncthreads();
        }
    }
}

// ---------------- CSR aggregate: per-node softmax-weighted sum + bias + relu ----
// 64 threads per node, 4 nodes per 256-thread block.
__global__ __launch_bounds__(256) void aggregate_kernel(const float* __restrict__ bias)
{
    const int node = blockIdx.x * 4 + (threadIdx.x >> 6);
    const int t    = threadIdx.x & 63;
    if (node >= N_NODES) return;

    const int beg = g_rowptr[node];
    const int cnt = g_count[node];
    const float dterm = g_d[node];

    float4 acc = make_float4(0.f, 0.f, 0.f, 0.f);
    float wsum = 0.f;

    for (int k = 0; k < cnt; k++) {
        const int src = g_ecol[beg + k];
        float e = g_s[src] + dterm;
        e = (e > 0.f) ? e : NEG_SLOPE * e;
        const float w = __expf(e);                  // softmax max-shift cancels exactly
        wsum += w;
        const float4 v = *reinterpret_cast<const float4*>(
            g_xw + (size_t)src * C_MID + t * 4);
        acc.x = fmaf(w, v.x, acc.x);
        acc.y = fmaf(w, v.y, acc.y);
        acc.z = fmaf(w, v.z, acc.z);
        acc.w = fmaf(w, v.w, acc.w);
    }

    const float inv = 1.f / wsum;                   // cnt >= 1 (self-loop)
    const float4 bb = reinterpret_cast<const float4*>(bias)[t];
    float4 o;
    o.x = fmaxf(fmaf(acc.x, inv, bb.x), 0.f);
    o.y = fmaxf(fmaf(acc.y, inv, bb.y), 0.f);
    o.z = fmaxf(fmaf(acc.z, inv, bb.z), 0.f);
    o.w = fmaxf(fmaf(acc.w, inv, bb.w), 0.f);
    *reinterpret_cast<float4*>(g_gat + (size_t)node * C_MID + t * 4) = o;
}

// ---------------- launch ----------------
extern "C" void kernel_launch(void* const* d_in, const int* in_sizes, int n_in,
                              void* d_out, int out_size)
{
    const float* x      = (const float*)d_in[0];
    const int*   ei     = (const int*)  d_in[1];
    const float* W      = (const float*)d_in[2];
    const float* a_src  = (const float*)d_in[3];
    const float* a_dst  = (const float*)d_in[4];
    const float* b      = (const float*)d_in[5];
    const float* W_fc2  = (const float*)d_in[6];
    const float* b_fc2  = (const float*)d_in[7];
    const float* W_out  = (const float*)d_in[8];
    const float* b_out  = (const float*)d_in[9];
    float* out = (float*)d_out;

    float *xw, *gat;
    cudaGetSymbolAddress((void**)&xw,  g_xw);
    cudaGetSymbolAddress((void**)&gat, g_gat);

    // 1) init small arrays
    init_kernel<<<(N_NODES + 255) / 256, 256>>>();

    // 2) CSR build
    hist_kernel<<<(E_TOT + 255) / 256, 256>>>(ei);
    scan1_kernel<<<N_SCAN_BLKS, SCAN_BLK>>>();
    scan2_kernel<<<1, 128>>>();
    scan3_kernel<<<(N_NODES + 255) / 256, 256>>>();
    scatter_kernel<<<(E_TOT + 255) / 256, 256>>>(ei);

    // 3) xw = x @ W with fused s/d attention dots
    {
        dim3 grid(C_MID / 128, (N_NODES + 127) / 128);
        sgemm_db<0><<<grid, 256>>>(x, W, nullptr, xw, a_src, a_dst, nullptr,
                                   N_NODES, C_MID, F_IN);
    }

    // 4) CSR aggregate with fused softmax + bias + relu
    aggregate_kernel<<<(N_NODES + 3) / 4, 256>>>(b);

    // 5+6) out = relu(h2 @ W_fc2 + b_fc2) @ W_out + b_out  (h3 never materialized)
    {
        dim3 grid(1, (N_NODES + 127) / 128);
        sgemm_db<1><<<grid, 256>>>(gat, W_fc2, b_fc2, nullptr, W_out, b_out, out,
                                   N_NODES, H_DIM, C_MID);
    }
}

// round 4
// speedup vs baseline: 1.5220x; 1.0894x over previous
#include <cuda_runtime.h>
#include <cstdint>

#define N_NODES 100000
#define N_EDGES 800000
#define F_IN    128
#define C_MID   256
#define H_DIM   128
#define O_DIM   6
#define NEG_SLOPE 0.2f

#define E_TOT (N_EDGES + N_NODES)
#define SCAN_BLK 1024
#define N_SCAN_BLKS ((N_NODES + SCAN_BLK - 1) / SCAN_BLK)   // 98

typedef unsigned long long u64;

// packed fp32x2 FMA (Blackwell FFMA2) — bit-exact two independent fp32 FMAs
#define FMA2(d, a, b) \
    asm("fma.rn.f32x2 %0, %1, %2, %0;" : "+l"(d) : "l"(a), "l"(b))
#define DUP2(d, s) \
    asm("mov.b64 %0, {%1, %1};" : "=l"(d) : "f"(s))
#define UNPK2(lo, hi, s) \
    asm("mov.b64 {%0, %1}, %2;" : "=f"(lo), "=f"(hi) : "l"(s))

// ---------------- device scratch ----------------
__device__ float g_xw[(size_t)N_NODES * C_MID];    // x @ W            102.4 MB
__device__ float g_gat[(size_t)N_NODES * C_MID];   // h2 (post relu)   102.4 MB
__device__ float g_s[N_NODES];
__device__ float g_d[N_NODES];
__device__ float g_w[E_TOT];                       // per-edge exp weight
__device__ float g_winv[N_NODES];                  // 1/denominator
__device__ int   g_count[N_NODES];
__device__ int   g_rowptr[N_NODES];
__device__ int   g_fill[N_NODES];
__device__ int   g_partial[N_SCAN_BLKS];
__device__ int   g_ecol[E_TOT];                    // src per CSR slot

// ---------------- init small arrays ----------------
__global__ void init_kernel() {
    const int i = blockIdx.x * blockDim.x + threadIdx.x;
    if (i < N_NODES) {
        g_count[i] = 0;
        g_fill[i]  = 0;
        g_s[i] = 0.f;
        g_d[i] = 0.f;
    }
}

// ---------------- CSR build ----------------
__global__ void hist_kernel(const int* __restrict__ ei) {
    const int e = blockIdx.x * blockDim.x + threadIdx.x;
    if (e >= E_TOT) return;
    const int dst = (e < N_EDGES) ? ei[N_EDGES + e] : (e - N_EDGES);
    atomicAdd(&g_count[dst], 1);
}

__global__ void scan1_kernel() {
    __shared__ int sh[SCAN_BLK];
    const int i = blockIdx.x * SCAN_BLK + threadIdx.x;
    const int v = (i < N_NODES) ? g_count[i] : 0;
    sh[threadIdx.x] = v;
    __syncthreads();
    for (int off = 1; off < SCAN_BLK; off <<= 1) {
        const int t = (threadIdx.x >= off) ? sh[threadIdx.x - off] : 0;
        __syncthreads();
        sh[threadIdx.x] += t;
        __syncthreads();
    }
    if (i < N_NODES) g_rowptr[i] = sh[threadIdx.x] - v;   // exclusive within block
    if (threadIdx.x == SCAN_BLK - 1) g_partial[blockIdx.x] = sh[SCAN_BLK - 1];
}

__global__ void scan2_kernel() {
    __shared__ int sh[128];
    const int t = threadIdx.x;
    const int v = (t < N_SCAN_BLKS) ? g_partial[t] : 0;
    sh[t] = v;
    __syncthreads();
    for (int off = 1; off < 128; off <<= 1) {
        const int u = (t >= off) ? sh[t - off] : 0;
        __syncthreads();
        sh[t] += u;
        __syncthreads();
    }
    if (t < N_SCAN_BLKS) g_partial[t] = sh[t] - v;        // exclusive of block sums
}

__global__ void scan3_kernel() {
    const int i = blockIdx.x * blockDim.x + threadIdx.x;
    if (i < N_NODES) g_rowptr[i] += g_partial[i >> 10];
}

__global__ void scatter_kernel(const int* __restrict__ ei) {
    const int e = blockIdx.x * blockDim.x + threadIdx.x;
    if (e >= E_TOT) return;
    int src, dst;
    if (e < N_EDGES) { src = ei[e]; dst = ei[N_EDGES + e]; }
    else             { src = dst = e - N_EDGES; }
    const int pos = g_rowptr[dst] + atomicAdd(&g_fill[dst], 1);
    g_ecol[pos] = src;
}

// ---------------- SGEMM 128x128, BK=8, 256 threads, 8x8/thread, FFMA2 core ----
// EPI 0: GEMM1 — store C=xw, plus fused per-row dots with a_src/a_dst -> g_s/g_d
// EPI 1: GEMM2 — relu(acc + bias) then fused 128->6 GEMM with W_out -> out
template <int EPI>
__global__ __launch_bounds__(256) void sgemm_db(
    const float* __restrict__ A, const float* __restrict__ B,
    const float* __restrict__ bias, float* __restrict__ C,
    const float* __restrict__ v1,   // EPI0: a_src   EPI1: W_out
    const float* __restrict__ v2,   // EPI0: a_dst   EPI1: b_out
    float* __restrict__ outp,       // EPI1: final output
    int M, int N, int K)
{
    constexpr int BM = 128, BN = 128, BK = 8;
    __shared__ float As[2][BK][BM];
    __shared__ float Bs[2][BK][BN];
    __shared__ float red[2][BM][17];

    const int tid = threadIdx.x;
    const int tx = tid % 16;
    const int ty = tid / 16;
    const int row0 = blockIdx.y * BM;
    const int col0 = blockIdx.x * BN;

    const int a_row = tid >> 1;          // 0..127
    const int a_col = (tid & 1) * 4;     // 0 or 4
    const int b_row = tid >> 5;          // 0..7
    const int b_col = (tid & 31) * 4;    // 0..124

    const int gr = row0 + a_row;
    const float* Aptr = A + (size_t)gr * K + a_col;
    const float* Bptr = B + (size_t)b_row * N + col0 + b_col;

    // acc2[i][jp] = (acc[i][2jp], acc[i][2jp+1]) packed fp32x2
    u64 acc2[8][4];
#pragma unroll
    for (int i = 0; i < 8; i++)
#pragma unroll
        for (int jp = 0; jp < 4; jp++) acc2[i][jp] = 0ULL;

    // prologue: stage tile 0
    float4 a_st = make_float4(0.f, 0.f, 0.f, 0.f);
    if (gr < M) a_st = *reinterpret_cast<const float4*>(Aptr);
    float4 b_st = *reinterpret_cast<const float4*>(Bptr);
    As[0][a_col + 0][a_row] = a_st.x;
    As[0][a_col + 1][a_row] = a_st.y;
    As[0][a_col + 2][a_row] = a_st.z;
    As[0][a_col + 3][a_row] = a_st.w;
    *reinterpret_cast<float4*>(&Bs[0][b_row][b_col]) = b_st;
    __syncthreads();

    const int ntiles = K / BK;
    for (int t = 0; t < ntiles; t++) {
        const int cur = t & 1;
        const int nxt = cur ^ 1;
        if (t + 1 < ntiles) {
            const int k0 = (t + 1) * BK;
            a_st = make_float4(0.f, 0.f, 0.f, 0.f);
            if (gr < M) a_st = *reinterpret_cast<const float4*>(Aptr + k0);
            b_st = *reinterpret_cast<const float4*>(Bptr + (size_t)k0 * N);
        }
#pragma unroll
        for (int k = 0; k < BK; k++) {
            u64 b2[4];
#pragma unroll
            for (int jp = 0; jp < 4; jp++)
                b2[jp] = *reinterpret_cast<const u64*>(&Bs[cur][k][tx * 8 + 2 * jp]);
#pragma unroll
            for (int i = 0; i < 8; i++) {
                const float av = As[cur][k][ty * 8 + i];
                u64 ad; DUP2(ad, av);
#pragma unroll
                for (int jp = 0; jp < 4; jp++)
                    FMA2(acc2[i][jp], ad, b2[jp]);
            }
        }
        if (t + 1 < ntiles) {
            As[nxt][a_col + 0][a_row] = a_st.x;
            As[nxt][a_col + 1][a_row] = a_st.y;
            As[nxt][a_col + 2][a_row] = a_st.z;
            As[nxt][a_col + 3][a_row] = a_st.w;
            *reinterpret_cast<float4*>(&Bs[nxt][b_row][b_col]) = b_st;
        }
        __syncthreads();
    }

    // unpack accumulators
    float acc[8][8];
#pragma unroll
    for (int i = 0; i < 8; i++)
#pragma unroll
        for (int jp = 0; jp < 4; jp++)
            UNPK2(acc[i][2 * jp], acc[i][2 * jp + 1], acc2[i][jp]);

    if (EPI == 0) {
#pragma unroll
        for (int i = 0; i < 8; i++) {
            const int r = row0 + ty * 8 + i;
            if (r >= M) break;
#pragma unroll
            for (int j = 0; j < 8; j += 4) {
                const int c = col0 + tx * 8 + j;
                float4 v = make_float4(acc[i][j], acc[i][j + 1],
                                       acc[i][j + 2], acc[i][j + 3]);
                *reinterpret_cast<float4*>(C + (size_t)r * N + c) = v;
            }
        }
        float av[8], dv[8];
#pragma unroll
        for (int j = 0; j < 8; j++) {
            av[j] = v1[col0 + tx * 8 + j];
            dv[j] = v2[col0 + tx * 8 + j];
        }
#pragma unroll
        for (int i = 0; i < 8; i++) {
            float ps = 0.f, pd = 0.f;
#pragma unroll
            for (int j = 0; j < 8; j++) {
                ps = fmaf(acc[i][j], av[j], ps);
                pd = fmaf(acc[i][j], dv[j], pd);
            }
            red[0][ty * 8 + i][tx] = ps;
            red[1][ty * 8 + i][tx] = pd;
        }
        __syncthreads();
        if (tid < 128) {
            float s = 0.f, d = 0.f;
#pragma unroll
            for (int t = 0; t < 16; t++) {
                s += red[0][tid][t];
                d += red[1][tid][t];
            }
            if (row0 + tid < M) {
                atomicAdd(&g_s[row0 + tid], s);
                atomicAdd(&g_d[row0 + tid], d);
            }
        }
    } else {
#pragma unroll
        for (int j = 0; j < 8; j++) {
            const float bb = bias[col0 + tx * 8 + j];
#pragma unroll
            for (int i = 0; i < 8; i++)
                acc[i][j] = fmaxf(acc[i][j] + bb, 0.f);
        }
        for (int o = 0; o < O_DIM; o += 2) {
            float w0[8], w1[8];
#pragma unroll
            for (int j = 0; j < 8; j++) {
                const int c = col0 + tx * 8 + j;
                w0[j] = v1[(size_t)c * O_DIM + o];
                w1[j] = v1[(size_t)c * O_DIM + o + 1];
            }
#pragma unroll
            for (int i = 0; i < 8; i++) {
                float p0 = 0.f, p1 = 0.f;
#pragma unroll
                for (int j = 0; j < 8; j++) {
                    p0 = fmaf(acc[i][j], w0[j], p0);
                    p1 = fmaf(acc[i][j], w1[j], p1);
                }
                red[0][ty * 8 + i][tx] = p0;
                red[1][ty * 8 + i][tx] = p1;
            }
            __syncthreads();
            if (tid < 128 && row0 + tid < M) {
                float s0 = 0.f, s1 = 0.f;
#pragma unroll
                for (int t = 0; t < 16; t++) {
                    s0 += red[0][tid][t];
                    s1 += red[1][tid][t];
                }
                outp[(size_t)(row0 + tid) * O_DIM + o]     = s0 + v2[o];
                outp[(size_t)(row0 + tid) * O_DIM + o + 1] = s1 + v2[o + 1];
            }
            __syncthreads();
        }
    }
}

// ---------------- edge weights: w[e] = exp(lrelu(s[src]+d[dst])), winv[n]=1/sum ----
// one warp per node
__global__ __launch_bounds__(256) void weight_kernel()
{
    const int node = blockIdx.x * 8 + (threadIdx.x >> 5);
    const int lane = threadIdx.x & 31;
    if (node >= N_NODES) return;
    const int beg = g_rowptr[node];
    const int cnt = g_count[node];
    const float dterm = g_d[node];
    float wsum = 0.f;
    for (int k = lane; k < cnt; k += 32) {
        const int src = g_ecol[beg + k];
        float e = g_s[src] + dterm;
        e = (e > 0.f) ? e : NEG_SLOPE * e;
        const float w = __expf(e);          // softmax max-shift cancels exactly
        g_w[beg + k] = w;
        wsum += w;
    }
#pragma unroll
    for (int o = 16; o > 0; o >>= 1)
        wsum += __shfl_xor_sync(0xffffffffu, wsum, o);
    if (lane == 0) g_winv[node] = 1.f / wsum;   // cnt >= 1 (self-loop)
}

// ---------------- CSR aggregate over one 128-col half: L2-resident gather ----
// 32 threads per node, 8 nodes per 256-thread block.
template <int HALF>
__global__ __launch_bounds__(256) void agg_half_kernel(const float* __restrict__ bias)
{
    const int node = blockIdx.x * 8 + (threadIdx.x >> 5);
    const int t    = threadIdx.x & 31;
    if (node >= N_NODES) return;

    const int beg = g_rowptr[node];
    const int cnt = g_count[node];

    float4 acc = make_float4(0.f, 0.f, 0.f, 0.f);
    for (int k = 0; k < cnt; k++) {
        const int src = g_ecol[beg + k];       // warp-broadcast
        const float w = g_w[beg + k];          // warp-broadcast
        const float4 v = *reinterpret_cast<const float4*>(
            g_xw + (size_t)src * C_MID + HALF * 128 + t * 4);
        acc.x = fmaf(w, v.x, acc.x);
        acc.y = fmaf(w, v.y, acc.y);
        acc.z = fmaf(w, v.z, acc.z);
        acc.w = fmaf(w, v.w, acc.w);
    }

    const float inv = g_winv[node];
    const float4 bb = reinterpret_cast<const float4*>(bias)[HALF * 32 + t];
    float4 o;
    o.x = fmaxf(fmaf(acc.x, inv, bb.x), 0.f);
    o.y = fmaxf(fmaf(acc.y, inv, bb.y), 0.f);
    o.z = fmaxf(fmaf(acc.z, inv, bb.z), 0.f);
    o.w = fmaxf(fmaf(acc.w, inv, bb.w), 0.f);
    *reinterpret_cast<float4*>(
        g_gat + (size_t)node * C_MID + HALF * 128 + t * 4) = o;
}

// ---------------- launch ----------------
extern "C" void kernel_launch(void* const* d_in, const int* in_sizes, int n_in,
                              void* d_out, int out_size)
{
    const float* x      = (const float*)d_in[0];
    const int*   ei     = (const int*)  d_in[1];
    const float* W      = (const float*)d_in[2];
    const float* a_src  = (const float*)d_in[3];
    const float* a_dst  = (const float*)d_in[4];
    const float* b      = (const float*)d_in[5];
    const float* W_fc2  = (const float*)d_in[6];
    const float* b_fc2  = (const float*)d_in[7];
    const float* W_out  = (const float*)d_in[8];
    const float* b_out  = (const float*)d_in[9];
    float* out = (float*)d_out;

    float *xw, *gat;
    cudaGetSymbolAddress((void**)&xw,  g_xw);
    cudaGetSymbolAddress((void**)&gat, g_gat);

    // 1) init
    init_kernel<<<(N_NODES + 255) / 256, 256>>>();

    // 2) CSR build
    hist_kernel<<<(E_TOT + 255) / 256, 256>>>(ei);
    scan1_kernel<<<N_SCAN_BLKS, SCAN_BLK>>>();
    scan2_kernel<<<1, 128>>>();
    scan3_kernel<<<(N_NODES + 255) / 256, 256>>>();
    scatter_kernel<<<(E_TOT + 255) / 256, 256>>>(ei);

    // 3) xw = x @ W with fused s/d attention dots (FFMA2 core)
    {
        dim3 grid(C_MID / 128, (N_NODES + 127) / 128);
        sgemm_db<0><<<grid, 256>>>(x, W, nullptr, xw, a_src, a_dst, nullptr,
                                   N_NODES, C_MID, F_IN);
    }

    // 4) edge softmax weights, then two L2-resident half-column gather passes
    weight_kernel<<<(N_NODES + 7) / 8, 256>>>();
    agg_half_kernel<0><<<(N_NODES + 7) / 8, 256>>>(b);
    agg_half_kernel<1><<<(N_NODES + 7) / 8, 256>>>(b);

    // 5+6) out = relu(h2 @ W_fc2 + b_fc2) @ W_out + b_out  (FFMA2 core, fused)
    {
        dim3 grid(1, (N_NODES + 127) / 128);
        sgemm_db<1><<<grid, 256>>>(gat, W_fc2, b_fc2, nullptr, W_out, b_out, out,
                                   N_NODES, H_DIM, C_MID);
    }
}

// round 5
// speedup vs baseline: 1.6721x; 1.0986x over previous
#include <cuda_runtime.h>
#include <cstdint>

#define N_NODES 100000
#define N_EDGES 800000
#define F_IN    128
#define C_MID   256
#define H_DIM   128
#define O_DIM   6
#define NEG_SLOPE 0.2f

#define E_TOT (N_EDGES + N_NODES)
#define SCAN_BLK 1024
#define N_SCAN_BLKS ((N_NODES + SCAN_BLK - 1) / SCAN_BLK)   // 98

typedef unsigned long long u64;

// packed fp32x2 FMA (Blackwell FFMA2) — bit-exact two independent fp32 FMAs
#define FMA2(d, a, b) \
    asm("fma.rn.f32x2 %0, %1, %2, %0;" : "+l"(d) : "l"(a), "l"(b))
#define DUP2(d, s) \
    asm("mov.b64 %0, {%1, %1};" : "=l"(d) : "f"(s))
#define UNPK2(lo, hi, s) \
    asm("mov.b64 {%0, %1}, %2;" : "=f"(lo), "=f"(hi) : "l"(s))

// ---------------- device scratch ----------------
__device__ float g_xw[(size_t)N_NODES * C_MID];    // x @ W            102.4 MB
__device__ float g_gat[(size_t)N_NODES * C_MID];   // h2 (post relu)   102.4 MB
__device__ float g_s[N_NODES];
__device__ float g_d[N_NODES];
__device__ float g_w[E_TOT];                       // per-edge exp weight
__device__ float g_winv[N_NODES];                  // 1/denominator
__device__ int   g_count[N_NODES];
__device__ int   g_rowptr[N_NODES];
__device__ int   g_fill[N_NODES];
__device__ int   g_partial[N_SCAN_BLKS];
__device__ int   g_ecol[E_TOT];                    // src per CSR slot

// ---------------- init small arrays ----------------
__global__ void init_kernel() {
    const int i = blockIdx.x * blockDim.x + threadIdx.x;
    if (i < N_NODES) {
        g_count[i] = 0;
        g_fill[i]  = 0;
        g_s[i] = 0.f;
        g_d[i] = 0.f;
    }
}

// ---------------- CSR build ----------------
__global__ void hist_kernel(const int* __restrict__ ei) {
    const int e = blockIdx.x * blockDim.x + threadIdx.x;
    if (e >= E_TOT) return;
    const int dst = (e < N_EDGES) ? ei[N_EDGES + e] : (e - N_EDGES);
    atomicAdd(&g_count[dst], 1);
}

__global__ void scan1_kernel() {
    __shared__ int sh[SCAN_BLK];
    const int i = blockIdx.x * SCAN_BLK + threadIdx.x;
    const int v = (i < N_NODES) ? g_count[i] : 0;
    sh[threadIdx.x] = v;
    __syncthreads();
    for (int off = 1; off < SCAN_BLK; off <<= 1) {
        const int t = (threadIdx.x >= off) ? sh[threadIdx.x - off] : 0;
        __syncthreads();
        sh[threadIdx.x] += t;
        __syncthreads();
    }
    if (i < N_NODES) g_rowptr[i] = sh[threadIdx.x] - v;   // exclusive within block
    if (threadIdx.x == SCAN_BLK - 1) g_partial[blockIdx.x] = sh[SCAN_BLK - 1];
}

__global__ void scan2_kernel() {
    __shared__ int sh[128];
    const int t = threadIdx.x;
    const int v = (t < N_SCAN_BLKS) ? g_partial[t] : 0;
    sh[t] = v;
    __syncthreads();
    for (int off = 1; off < 128; off <<= 1) {
        const int u = (t >= off) ? sh[t - off] : 0;
        __syncthreads();
        sh[t] += u;
        __syncthreads();
    }
    if (t < N_SCAN_BLKS) g_partial[t] = sh[t] - v;        // exclusive of block sums
}

__global__ void scan3_kernel() {
    const int i = blockIdx.x * blockDim.x + threadIdx.x;
    if (i < N_NODES) g_rowptr[i] += g_partial[i >> 10];
}

__global__ void scatter_kernel(const int* __restrict__ ei) {
    const int e = blockIdx.x * blockDim.x + threadIdx.x;
    if (e >= E_TOT) return;
    int src, dst;
    if (e < N_EDGES) { src = ei[e]; dst = ei[N_EDGES + e]; }
    else             { src = dst = e - N_EDGES; }
    const int pos = g_rowptr[dst] + atomicAdd(&g_fill[dst], 1);
    g_ecol[pos] = src;
}

// ---------------- SGEMM 128x128, BK=8, 256 threads, 8x8/thread ----------------
// FFMA2 core, conflict-free LDS: thread columns are tx*2 + 32*jp + u.
// EPI 0: GEMM1 — store C=xw, plus fused per-row dots with a_src/a_dst -> g_s/g_d
// EPI 1: GEMM2 — relu(acc + bias) then fused 128->6 GEMM with W_out -> out
template <int EPI>
__global__ __launch_bounds__(256) void sgemm_db(
    const float* __restrict__ A, const float* __restrict__ B,
    const float* __restrict__ bias, float* __restrict__ C,
    const float* __restrict__ v1,   // EPI0: a_src   EPI1: W_out
    const float* __restrict__ v2,   // EPI0: a_dst   EPI1: b_out
    float* __restrict__ outp,       // EPI1: final output
    int M, int N, int K)
{
    constexpr int BM = 128, BN = 128, BK = 8;
    __shared__ float As[2][BK][BM];
    __shared__ float Bs[2][BK][BN];
    __shared__ float red[2][BM][17];

    const int tid = threadIdx.x;
    const int tx = tid % 16;
    const int ty = tid / 16;
    const int row0 = blockIdx.y * BM;
    const int col0 = blockIdx.x * BN;

    const int a_row = tid >> 1;          // 0..127
    const int a_col = (tid & 1) * 4;     // 0 or 4
    const int b_row = tid >> 5;          // 0..7
    const int b_col = (tid & 31) * 4;    // 0..124

    const int gr = row0 + a_row;
    const float* Aptr = A + (size_t)gr * K + a_col;
    const float* Bptr = B + (size_t)b_row * N + col0 + b_col;

    // acc2[i][jp] = packed pair for columns (tx*2 + 32*jp + {0,1})
    u64 acc2[8][4];
#pragma unroll
    for (int i = 0; i < 8; i++)
#pragma unroll
        for (int jp = 0; jp < 4; jp++) acc2[i][jp] = 0ULL;

    // prologue: stage tile 0
    float4 a_st = make_float4(0.f, 0.f, 0.f, 0.f);
    if (gr < M) a_st = *reinterpret_cast<const float4*>(Aptr);
    float4 b_st = *reinterpret_cast<const float4*>(Bptr);
    As[0][a_col + 0][a_row] = a_st.x;
    As[0][a_col + 1][a_row] = a_st.y;
    As[0][a_col + 2][a_row] = a_st.z;
    As[0][a_col + 3][a_row] = a_st.w;
    *reinterpret_cast<float4*>(&Bs[0][b_row][b_col]) = b_st;
    __syncthreads();

    const int ntiles = K / BK;
    for (int t = 0; t < ntiles; t++) {
        const int cur = t & 1;
        const int nxt = cur ^ 1;
        if (t + 1 < ntiles) {
            const int k0 = (t + 1) * BK;
            a_st = make_float4(0.f, 0.f, 0.f, 0.f);
            if (gr < M) a_st = *reinterpret_cast<const float4*>(Aptr + k0);
            b_st = *reinterpret_cast<const float4*>(Bptr + (size_t)k0 * N);
        }
#pragma unroll
        for (int k = 0; k < BK; k++) {
            // B fragment: 4 LDS.64, lanes at 8B stride -> conflict-free
            u64 b2[4];
#pragma unroll
            for (int jp = 0; jp < 4; jp++)
                b2[jp] = *reinterpret_cast<const u64*>(
                    &Bs[cur][k][tx * 2 + 32 * jp]);
            // A fragment: 4 LDS.64 (row pairs), 2 distinct addrs/warp -> broadcast
            u64 a2[4];
#pragma unroll
            for (int ip = 0; ip < 4; ip++)
                a2[ip] = *reinterpret_cast<const u64*>(
                    &As[cur][k][ty * 8 + 2 * ip]);
#pragma unroll
            for (int ip = 0; ip < 4; ip++) {
                float alo, ahi;
                UNPK2(alo, ahi, a2[ip]);
                u64 d0, d1;
                DUP2(d0, alo);
                DUP2(d1, ahi);
#pragma unroll
                for (int jp = 0; jp < 4; jp++) {
                    FMA2(acc2[2 * ip][jp], d0, b2[jp]);
                    FMA2(acc2[2 * ip + 1][jp], d1, b2[jp]);
                }
            }
        }
        if (t + 1 < ntiles) {
            As[nxt][a_col + 0][a_row] = a_st.x;
            As[nxt][a_col + 1][a_row] = a_st.y;
            As[nxt][a_col + 2][a_row] = a_st.z;
            As[nxt][a_col + 3][a_row] = a_st.w;
            *reinterpret_cast<float4*>(&Bs[nxt][b_row][b_col]) = b_st;
        }
        __syncthreads();
    }

    if (EPI == 0) {
        // store C: packed 8B stores, 16 lanes x 8B contiguous per jp -> coalesced
#pragma unroll
        for (int i = 0; i < 8; i++) {
            const int r = row0 + ty * 8 + i;
            if (r >= M) break;
#pragma unroll
            for (int jp = 0; jp < 4; jp++) {
                const int c = col0 + tx * 2 + 32 * jp;
                *reinterpret_cast<u64*>(C + (size_t)r * N + c) = acc2[i][jp];
            }
        }
        // fused attention halves
        float av[8], dv[8], acc[8];
#pragma unroll
        for (int jp = 0; jp < 4; jp++) {
            const int c = col0 + tx * 2 + 32 * jp;
            av[2 * jp]     = v1[c];
            av[2 * jp + 1] = v1[c + 1];
            dv[2 * jp]     = v2[c];
            dv[2 * jp + 1] = v2[c + 1];
        }
#pragma unroll
        for (int i = 0; i < 8; i++) {
#pragma unroll
            for (int jp = 0; jp < 4; jp++)
                UNPK2(acc[2 * jp], acc[2 * jp + 1], acc2[i][jp]);
            float ps = 0.f, pd = 0.f;
#pragma unroll
            for (int j = 0; j < 8; j++) {
                ps = fmaf(acc[j], av[j], ps);
                pd = fmaf(acc[j], dv[j], pd);
            }
            red[0][ty * 8 + i][tx] = ps;
            red[1][ty * 8 + i][tx] = pd;
        }
        __syncthreads();
        if (tid < 128) {
            float s = 0.f, d = 0.f;
#pragma unroll
            for (int t = 0; t < 16; t++) {
                s += red[0][tid][t];
                d += red[1][tid][t];
            }
            if (row0 + tid < M) {
                atomicAdd(&g_s[row0 + tid], s);
                atomicAdd(&g_d[row0 + tid], d);
            }
        }
    } else {
        // EPI1: relu(acc + bias), then out = h3 @ W_out + b_out (no C store)
        float acc[8][8];
#pragma unroll
        for (int jp = 0; jp < 4; jp++) {
            const int c = col0 + tx * 2 + 32 * jp;
            const float b0 = bias[c], b1 = bias[c + 1];
#pragma unroll
            for (int i = 0; i < 8; i++) {
                float lo, hi;
                UNPK2(lo, hi, acc2[i][jp]);
                acc[i][2 * jp]     = fmaxf(lo + b0, 0.f);
                acc[i][2 * jp + 1] = fmaxf(hi + b1, 0.f);
            }
        }
        for (int o = 0; o < O_DIM; o += 2) {
            float w0[8], w1[8];
#pragma unroll
            for (int jp = 0; jp < 4; jp++) {
                const int c = col0 + tx * 2 + 32 * jp;
                w0[2 * jp]     = v1[(size_t)c * O_DIM + o];
                w0[2 * jp + 1] = v1[(size_t)(c + 1) * O_DIM + o];
                w1[2 * jp]     = v1[(size_t)c * O_DIM + o + 1];
                w1[2 * jp + 1] = v1[(size_t)(c + 1) * O_DIM + o + 1];
            }
#pragma unroll
            for (int i = 0; i < 8; i++) {
                float p0 = 0.f, p1 = 0.f;
#pragma unroll
                for (int j = 0; j < 8; j++) {
                    p0 = fmaf(acc[i][j], w0[j], p0);
                    p1 = fmaf(acc[i][j], w1[j], p1);
                }
                red[0][ty * 8 + i][tx] = p0;
                red[1][ty * 8 + i][tx] = p1;
            }
            __syncthreads();
            if (tid < 128 && row0 + tid < M) {
                float s0 = 0.f, s1 = 0.f;
#pragma unroll
                for (int t = 0; t < 16; t++) {
                    s0 += red[0][tid][t];
                    s1 += red[1][tid][t];
                }
                outp[(size_t)(row0 + tid) * O_DIM + o]     = s0 + v2[o];
                outp[(size_t)(row0 + tid) * O_DIM + o + 1] = s1 + v2[o + 1];
            }
            __syncthreads();
        }
    }
}

// ---------------- edge weights: w[e] = exp(lrelu(s[src]+d[dst])), winv[n]=1/sum ----
__global__ __launch_bounds__(256) void weight_kernel()
{
    const int node = blockIdx.x * 8 + (threadIdx.x >> 5);
    const int lane = threadIdx.x & 31;
    if (node >= N_NODES) return;
    const int beg = g_rowptr[node];
    const int cnt = g_count[node];
    const float dterm = g_d[node];
    float wsum = 0.f;
    for (int k = lane; k < cnt; k += 32) {
        const int src = g_ecol[beg + k];
        float e = g_s[src] + dterm;
        e = (e > 0.f) ? e : NEG_SLOPE * e;
        const float w = __expf(e);          // softmax max-shift cancels exactly
        g_w[beg + k] = w;
        wsum += w;
    }
#pragma unroll
    for (int o = 16; o > 0; o >>= 1)
        wsum += __shfl_xor_sync(0xffffffffu, wsum, o);
    if (lane == 0) g_winv[node] = 1.f / wsum;   // cnt >= 1 (self-loop)
}

// ---------------- CSR aggregate over one 128-col half: L2-resident gather ----
template <int HALF>
__global__ __launch_bounds__(256) void agg_half_kernel(const float* __restrict__ bias)
{
    const int node = blockIdx.x * 8 + (threadIdx.x >> 5);
    const int t    = threadIdx.x & 31;
    if (node >= N_NODES) return;

    const int beg = g_rowptr[node];
    const int cnt = g_count[node];

    float4 acc = make_float4(0.f, 0.f, 0.f, 0.f);
    for (int k = 0; k < cnt; k++) {
        const int src = g_ecol[beg + k];       // warp-broadcast
        const float w = g_w[beg + k];          // warp-broadcast
        const float4 v = *reinterpret_cast<const float4*>(
            g_xw + (size_t)src * C_MID + HALF * 128 + t * 4);
        acc.x = fmaf(w, v.x, acc.x);
        acc.y = fmaf(w, v.y, acc.y);
        acc.z = fmaf(w, v.z, acc.z);
        acc.w = fmaf(w, v.w, acc.w);
    }

    const float inv = g_winv[node];
    const float4 bb = reinterpret_cast<const float4*>(bias)[HALF * 32 + t];
    float4 o;
    o.x = fmaxf(fmaf(acc.x, inv, bb.x), 0.f);
    o.y = fmaxf(fmaf(acc.y, inv, bb.y), 0.f);
    o.z = fmaxf(fmaf(acc.z, inv, bb.z), 0.f);
    o.w = fmaxf(fmaf(acc.w, inv, bb.w), 0.f);
    *reinterpret_cast<float4*>(
        g_gat + (size_t)node * C_MID + HALF * 128 + t * 4) = o;
}

// ---------------- launch ----------------
extern "C" void kernel_launch(void* const* d_in, const int* in_sizes, int n_in,
                              void* d_out, int out_size)
{
    const float* x      = (const float*)d_in[0];
    const int*   ei     = (const int*)  d_in[1];
    const float* W      = (const float*)d_in[2];
    const float* a_src  = (const float*)d_in[3];
    const float* a_dst  = (const float*)d_in[4];
    const float* b      = (const float*)d_in[5];
    const float* W_fc2  = (const float*)d_in[6];
    const float* b_fc2  = (const float*)d_in[7];
    const float* W_out  = (const float*)d_in[8];
    const float* b_out  = (const float*)d_in[9];
    float* out = (float*)d_out;

    float *xw, *gat;
    cudaGetSymbolAddress((void**)&xw,  g_xw);
    cudaGetSymbolAddress((void**)&gat, g_gat);

    // 1) init
    init_kernel<<<(N_NODES + 255) / 256, 256>>>();

    // 2) CSR build
    hist_kernel<<<(E_TOT + 255) / 256, 256>>>(ei);
    scan1_kernel<<<N_SCAN_BLKS, SCAN_BLK>>>();
    scan2_kernel<<<1, 128>>>();
    scan3_kernel<<<(N_NODES + 255) / 256, 256>>>();
    scatter_kernel<<<(E_TOT + 255) / 256, 256>>>(ei);

    // 3) xw = x @ W with fused s/d attention dots (conflict-free FFMA2 core)
    {
        dim3 grid(C_MID / 128, (N_NODES + 127) / 128);
        sgemm_db<0><<<grid, 256>>>(x, W, nullptr, xw, a_src, a_dst, nullptr,
                                   N_NODES, C_MID, F_IN);
    }

    // 4) edge softmax weights, then two L2-resident half-column gather passes
    weight_kernel<<<(N_NODES + 7) / 8, 256>>>();
    agg_half_kernel<0><<<(N_NODES + 7) / 8, 256>>>(b);
    agg_half_kernel<1><<<(N_NODES + 7) / 8, 256>>>(b);

    // 5+6) out = relu(h2 @ W_fc2 + b_fc2) @ W_out + b_out  (fused, h3 never stored)
    {
        dim3 grid(1, (N_NODES + 127) / 128);
        sgemm_db<1><<<grid, 256>>>(gat, W_fc2, b_fc2, nullptr, W_out, b_out, out,
                                   N_NODES, H_DIM, C_MID);
    }
}